// round 17
// baseline (speedup 1.0000x reference)
#include <cuda_runtime.h>
#include <cstdint>

// Problem constants
#define B_ROWS   2048
#define DIM_IN   4096
#define DIM_OUT  4096
#define KW       128          // DIM_IN / 32 packed words

// Scratch (allocation-free rule: __device__ globals)
__device__ __align__(16) uint32_t g_xp[B_ROWS * KW];     // packed x [b][w]
__device__ __align__(16) uint32_t g_mp[KW * DIM_OUT];    // packed masks, TRANSPOSED [w][j]

__device__ __forceinline__ uint32_t smem_u32(const void* p) {
    uint32_t a;
    asm("{ .reg .u64 t; cvta.to.shared.u64 t, %1; cvt.u32.u64 %0, t; }" : "=r"(a) : "l"(p));
    return a;
}
__device__ __forceinline__ void cp16(uint32_t dst, const void* src) {
    asm volatile("cp.async.cg.shared.global [%0], [%1], 16;" :: "r"(dst), "l"(src) : "memory");
}
__device__ __forceinline__ void cp_commit() { asm volatile("cp.async.commit_group;" ::: "memory"); }
__device__ __forceinline__ void cp_wait1()  { asm volatile("cp.async.wait_group 1;" ::: "memory"); }
__device__ __forceinline__ void cp_wait0()  { asm volatile("cp.async.wait_group 0;" ::: "memory"); }

// ---------------------------------------------------------------------------
// Fused pack kernel. First PM_BLOCKS blocks pack masks (heavier — scheduled
// first); remaining blocks pack x. Overlaps both DRAM read streams.
// ---------------------------------------------------------------------------
#define PM_THREADS (KW * DIM_OUT / 4)          // 131072 (4 j per thread)
#define PM_BLOCKS  (PM_THREADS / 256)          // 512
#define PX_THREADS (B_ROWS * KW * 4)           // 1048576 (one byte per thread)
#define PX_BLOCKS  (PX_THREADS / 256)          // 4096

__global__ __launch_bounds__(256)
void pack_both_kernel(const int4* __restrict__ x4, const uint32_t* __restrict__ m) {
    if (blockIdx.x < PM_BLOCKS) {
        // ---- pack masks -> g_mp[w][j], 4 columns per thread ----
        int t  = blockIdx.x * 256 + threadIdx.x;   // [0, PM_THREADS)
        int w  = t >> 10;                          // / (DIM_OUT/4)
        int jq = (t & 1023) * 4;
        const uint32_t* p = m + (size_t)(w * 32) * DIM_OUT + jq;
        uint32_t w0 = 0, w1 = 0, w2 = 0, w3 = 0;
#pragma unroll
        for (int i = 0; i < 32; i++) {
            uint4 v = *reinterpret_cast<const uint4*>(p + (size_t)i * DIM_OUT);
            w0 |= ((unsigned)(v.x != 0u)) << i;
            w1 |= ((unsigned)(v.y != 0u)) << i;
            w2 |= ((unsigned)(v.z != 0u)) << i;
            w3 |= ((unsigned)(v.w != 0u)) << i;
        }
        *reinterpret_cast<uint4*>(&g_mp[w * DIM_OUT + jq]) = make_uint4(w0, w1, w2, w3);
    } else {
        // ---- pack x -> g_xp, one byte (8 values) per thread ----
        int t = (blockIdx.x - PM_BLOCKS) * 256 + threadIdx.x;  // byte index
        const int4* p = x4 + (size_t)t * 2;
        int4 v0 = p[0], v1 = p[1];
        unsigned b = (unsigned)v0.x | ((unsigned)v0.y << 1) | ((unsigned)v0.z << 2) |
                     ((unsigned)v0.w << 3) | ((unsigned)v1.x << 4) | ((unsigned)v1.y << 5) |
                     ((unsigned)v1.z << 6) | ((unsigned)v1.w << 7);
        reinterpret_cast<uint8_t*>(g_xp)[t] = (uint8_t)b;
    }
}

// ---------------------------------------------------------------------------
// XNOR-popcount GEMM with CSA compression.
// Triple-buffered cp.async (prefetch distance 1) -> ONE barrier per K-chunk.
// j-outer inner loop to cap live registers (<=64 -> 4 CTAs/SM).
// ---------------------------------------------------------------------------
#define BM 64
#define BN 64
#define CW 16
#define NCHUNK (KW / CW)       // 8
#define XS_STRIDE (CW + 4)     // 20 words; rows 80B (16B-aligned)
#define MS_STRIDE (BN + 4)     // 68 words; rows 272B (16B-aligned)

__global__ __launch_bounds__(256, 4)
void xnor_gemm_kernel(const int* __restrict__ thr, float* __restrict__ out) {
    __shared__ uint32_t xs[3][BM][XS_STRIDE];   // [buf][row][w]
    __shared__ uint32_t ms[3][CW][MS_STRIDE];   // [buf][w][col]

    const int tid  = threadIdx.x;
    const int tx   = tid & 15;      // 16 col-groups
    const int ty   = tid >> 4;      // 16 row-groups
    const int row0 = blockIdx.y * BM;
    const int col0 = blockIdx.x * BN;

    // cp.async assignment: one 16B chunk each into xs and ms per stage
    const int xr = tid >> 2;            // 0..63
    const int xw = (tid & 3) * 4;       // 0,4,8,12
    const int mw = tid >> 4;            // 0..15
    const int mj = (tid & 15) * 4;      // 0..60

    auto copy_chunk = [&](int buf, int it) {
        int w0 = it * CW;
        cp16(smem_u32(&xs[buf][xr][xw]), &g_xp[(row0 + xr) * KW + w0 + xw]);
        cp16(smem_u32(&ms[buf][mw][mj]), &g_mp[(w0 + mw) * DIM_OUT + col0 + mj]);
        cp_commit();
    };

    copy_chunk(0, 0);

    int acc[4][4] = {};

    for (int it = 0; it < NCHUNK; it++) {
        const int buf = it % 3;
        if (it + 1 < NCHUNK) { copy_chunk((it + 1) % 3, it + 1); cp_wait1(); }
        else                 { cp_wait0(); }
        __syncthreads();    // single barrier: buffer (it+1)%3 never collides
                            // with any buffer under compute at warp skew <= 1

#pragma unroll
        for (int g = 0; g < CW / 8; g++) {
            uint32_t a[4][8];
#pragma unroll
            for (int i = 0; i < 4; i++) {
                uint4 v0 = *reinterpret_cast<const uint4*>(&xs[buf][ty * 4 + i][g * 8]);
                uint4 v1 = *reinterpret_cast<const uint4*>(&xs[buf][ty * 4 + i][g * 8 + 4]);
                a[i][0] = v0.x; a[i][1] = v0.y; a[i][2] = v0.z; a[i][3] = v0.w;
                a[i][4] = v1.x; a[i][5] = v1.y; a[i][6] = v1.z; a[i][7] = v1.w;
            }
#pragma unroll
            for (int j = 0; j < 4; j++) {
                // load one b column-word set, consume across all 4 rows
                uint32_t b[8];
#pragma unroll
                for (int w = 0; w < 8; w++) b[w] = ms[buf][g * 8 + w][tx * 4 + j];
#pragma unroll
                for (int i = 0; i < 4; i++) {
                    uint32_t x0 = a[i][0] ^ b[0], x1 = a[i][1] ^ b[1];
                    uint32_t x2 = a[i][2] ^ b[2], x3 = a[i][3] ^ b[3];
                    uint32_t x4 = a[i][4] ^ b[4], x5 = a[i][5] ^ b[5];
                    uint32_t x6 = a[i][6] ^ b[6], x7 = a[i][7] ^ b[7];
                    // level 1: two full adders + one half adder (LOP3-friendly)
                    uint32_t s1 = x0 ^ x1 ^ x2, c1 = (x0 & x1) | (x2 & (x0 | x1));
                    uint32_t s2 = x3 ^ x4 ^ x5, c2 = (x3 & x4) | (x5 & (x3 | x4));
                    uint32_t s3 = x6 ^ x7,      c3 = x6 & x7;
                    // level 2
                    uint32_t S  = s1 ^ s2 ^ s3, C  = (s1 & s2) | (s3 & (s1 | s2));
                    uint32_t S2 = c1 ^ c2 ^ c3, C2 = (c1 & c2) | (c3 & (c1 | c2));
                    acc[i][j] += __popc(S) + ((__popc(C) + __popc(S2)) << 1)
                               + (__popc(C2) << 2);
                }
            }
        }
        __syncthreads();    // protect buf before it is refilled two iters later
    }

    // Epilogue: matches = DIM_IN - acc; out = matches > thr  <=>  acc < DIM_IN - thr
    const int cbase = col0 + tx * 4;
    int u[4];
#pragma unroll
    for (int j = 0; j < 4; j++) u[j] = DIM_IN - thr[cbase + j];

#pragma unroll
    for (int i = 0; i < 4; i++) {
        int r = row0 + ty * 4 + i;
        float4 v;
        v.x = (acc[i][0] < u[0]) ? 1.0f : 0.0f;
        v.y = (acc[i][1] < u[1]) ? 1.0f : 0.0f;
        v.z = (acc[i][2] < u[2]) ? 1.0f : 0.0f;
        v.w = (acc[i][3] < u[3]) ? 1.0f : 0.0f;
        *reinterpret_cast<float4*>(out + (size_t)r * DIM_OUT + cbase) = v;
    }
}

// ---------------------------------------------------------------------------
extern "C" void kernel_launch(void* const* d_in, const int* in_sizes, int n_in,
                              void* d_out, int out_size) {
    const int4*     x4   = (const int4*)d_in[0];      // (B, DIM_IN) int32 0/1
    const uint32_t* mask = (const uint32_t*)d_in[1];  // (DIM_IN, DIM_OUT) 4-byte 0/1
    const int*      thr  = (const int*)d_in[2];       // (DIM_OUT,) int32
    float*          out  = (float*)d_out;             // (B, DIM_OUT) float 0/1

    // 1) fused pack (masks first, then x)
    pack_both_kernel<<<PM_BLOCKS + PX_BLOCKS, 256>>>(x4, mask);
    // 2) CSA GEMM + epilogue
    {
        dim3 grid(DIM_OUT / BN, B_ROWS / BM);
        xnor_gemm_kernel<<<grid, 256>>>(thr, out);
    }
}